// round 17
// baseline (speedup 1.0000x reference)
#include <cuda_runtime.h>
#include <cuda_fp16.h>
#include <cstdint>
#include <math.h>

#define Bx     256
#define Tx     128
#define ENCX   1024
#define UX     1024
#define EMBX   512
#define VOCABX 32000
#define XDIM   1536
#define WXN    3072
#define GXN    2048
#define HSTRW  36          // fp16 tile row stride in 32-bit words (144B rows)

// ---------------- scratch ----------------
__device__ float g_hw2[Bx * UX];
__device__ float g_S[Bx * Tx];
__device__ float g_attn[Bx * Tx];
__device__ float g_xt[Bx * XDIM];
__device__ float g_gx[Bx * GXN];
__device__ __half g_stateh[Bx * UX];        // fp16 state (logits A)
__device__ __half g_W1th[UX * ENCX];        // W1 transposed (N,K), fp16
__device__ __half g_ench[Bx * Tx * ENCX];   // enc, fp16
__device__ __half g_Wfch[UX * VOCABX];      // Wfc, fp16 [k][n]

__device__ __forceinline__ uint32_t smem_to_u32(const void* p) {
    uint32_t a;
    asm("{ .reg .u64 t; cvta.to.shared.u64 t, %1; cvt.u32.u64 %0, t; }"
        : "=r"(a) : "l"(p));
    return a;
}
__device__ __forceinline__ void cp_async16(uint32_t s, const void* g) {
    asm volatile("cp.async.ca.shared.global [%0], [%1], 16;" :: "r"(s), "l"(g));
}
#define CP_COMMIT() asm volatile("cp.async.commit_group;")
#define CP_WAIT0()  asm volatile("cp.async.wait_group 0;")

__device__ __forceinline__ void mma_f16(float* c, const unsigned* a, const unsigned* b) {
    asm volatile(
        "mma.sync.aligned.m16n8k16.row.col.f32.f16.f16.f32 "
        "{%0,%1,%2,%3}, {%4,%5,%6,%7}, {%8,%9}, {%0,%1,%2,%3};"
        : "+f"(c[0]), "+f"(c[1]), "+f"(c[2]), "+f"(c[3])
        : "r"(a[0]), "r"(a[1]), "r"(a[2]), "r"(a[3]), "r"(b[0]), "r"(b[1]));
}
__device__ __forceinline__ void ldmatrix_x4_trans(unsigned& r0, unsigned& r1,
                                                  unsigned& r2, unsigned& r3,
                                                  uint32_t addr) {
    asm volatile(
        "ldmatrix.sync.aligned.m8n8.x4.trans.shared.b16 {%0,%1,%2,%3}, [%4];"
        : "=r"(r0), "=r"(r1), "=r"(r2), "=r"(r3) : "r"(addr));
}

// ================= fused prologue: one launch, role by block range ===========
// [0,16384)      conv enc -> g_ench (fp16), 8 elems/thread
// [16384,32384)  conv Wfc -> g_Wfch (fp16)
// [32384,32512)  zero g_S
// [32512,33536)  transpose W1 -> g_W1th (N,K) fp16
// [33536,33600)  hw2 = hidden@W2 + b1 + b2 (full-K per tile, direct store)
#define PB_ENC   16384
#define PB_WFC   32384
#define PB_ZS    32512
#define PB_TW1   33536
#define PB_TOTAL 33600

__global__ void __launch_bounds__(256) k_prologue(
    const float* __restrict__ enc, const float* __restrict__ Wfc,
    const float* __restrict__ b1, const float* __restrict__ b2,
    const float* __restrict__ W1, const float* __restrict__ hidden,
    const float* __restrict__ W2) {
    __shared__ float smA[16][64];
    __shared__ float smB[16][64];
    __shared__ float smT[32][33];
    int bid = blockIdx.x;
    int tid = threadIdx.x;

    if (bid < PB_ENC) {
        size_t i = ((size_t)bid * 256 + tid) * 8;
        float4 v0 = *(const float4*)(enc + i);
        float4 v1 = *(const float4*)(enc + i + 4);
        __half2 h[4];
        h[0] = __floats2half2_rn(v0.x, v0.y);
        h[1] = __floats2half2_rn(v0.z, v0.w);
        h[2] = __floats2half2_rn(v1.x, v1.y);
        h[3] = __floats2half2_rn(v1.z, v1.w);
        *(uint4*)(g_ench + i) = *(const uint4*)h;
    } else if (bid < PB_WFC) {
        size_t i = ((size_t)(bid - PB_ENC) * 256 + tid) * 8;
        float4 v0 = *(const float4*)(Wfc + i);
        float4 v1 = *(const float4*)(Wfc + i + 4);
        __half2 h[4];
        h[0] = __floats2half2_rn(v0.x, v0.y);
        h[1] = __floats2half2_rn(v0.z, v0.w);
        h[2] = __floats2half2_rn(v1.x, v1.y);
        h[3] = __floats2half2_rn(v1.z, v1.w);
        *(uint4*)(g_Wfch + i) = *(const uint4*)h;
    } else if (bid < PB_ZS) {
        int i = (bid - PB_WFC) * 256 + tid;
        g_S[i] = 0.f;
    } else if (bid < PB_TW1) {
        int r = bid - PB_ZS;                   // 0..1023
        int gx = (r & 31) * 32, gy = (r >> 5) * 32;
        int x = tid & 31, y0 = tid >> 5;       // x 0..31, y0 0..7
#pragma unroll
        for (int i = 0; i < 32; i += 8)
            smT[y0 + i][x] = W1[(size_t)(gy + y0 + i) * UX + gx + x];
        __syncthreads();
#pragma unroll
        for (int i = 0; i < 32; i += 8)
            g_W1th[(size_t)(gx + y0 + i) * ENCX + gy + x] =
                __float2half_rn(smT[x][y0 + i]);
    } else {
        int r = bid - PB_TW1;                  // 0..63
        int m0 = (r >> 4) * 64, n0 = (r & 15) * 64;
        int ar = tid >> 2, ac = (tid & 3) << 2;
        int br = tid >> 4, bc = (tid & 15) << 2;
        int ty = tid >> 4, tx = tid & 15;
        float acc[4][4] = {};
        for (int k0 = 0; k0 < UX; k0 += 16) {
            float4 av = *(const float4*)&hidden[(size_t)(m0 + ar) * UX + k0 + ac];
            float4 bv = *(const float4*)&W2[(size_t)(k0 + br) * UX + n0 + bc];
            __syncthreads();
            smA[ac + 0][ar] = av.x; smA[ac + 1][ar] = av.y;
            smA[ac + 2][ar] = av.z; smA[ac + 3][ar] = av.w;
            *(float4*)&smB[br][bc] = bv;
            __syncthreads();
#pragma unroll
            for (int k = 0; k < 16; k++) {
                float ra[4], rb[4];
#pragma unroll
                for (int i = 0; i < 4; i++) ra[i] = smA[k][ty * 4 + i];
#pragma unroll
                for (int j = 0; j < 4; j++) rb[j] = smB[k][tx * 4 + j];
#pragma unroll
                for (int i = 0; i < 4; i++)
#pragma unroll
                    for (int j = 0; j < 4; j++) acc[i][j] += ra[i] * rb[j];
            }
        }
#pragma unroll
        for (int i = 0; i < 4; i++) {
            int m = m0 + ty * 4 + i;
#pragma unroll
            for (int j = 0; j < 4; j++) {
                int n = n0 + tx * 4 + j;
                g_hw2[(size_t)m * UX + n] = acc[i][j] + b1[n] + b2[n];
            }
        }
    }
}

// ================= score GEMM (mma.sync fp16 m16n8k16 + cp.async) ============
// Block tile 128(m) x 256(n), BK=64. 256 threads, 8 warps 2(m) x 4(n),
// warptile 64x64. A [m][k] & B [n][k] fp16 tiles, 144B rows. 2 stages.
#define SC_BS_OFF   36864
#define SC_STAGE_A  18432
#define SC_STAGE_B  36864
#define SC_HW2_OFF  110592
#define SC_VS_OFF   111616
#define SC_RED_OFF  112640
#define SC_SMEM_BYTES 115200
#define SC_NKT      16

__global__ void __launch_bounds__(256, 1)
k_score_tc(const float* __restrict__ V) {
    extern __shared__ char smraw[];
    uint32_t smu = smem_to_u32(smraw);
    float* hw2s  = (float*)(smraw + SC_HW2_OFF);
    float* Vs    = (float*)(smraw + SC_VS_OFF);
    float* red   = (float*)(smraw + SC_RED_OFF);

    int tid = threadIdx.x;
    int lane = tid & 31, wid = tid >> 5;
    int warp_m = wid & 1, warp_n = wid >> 1;
    int g = lane >> 2, tig = lane & 3;
    int b = blockIdx.y;
    int n0 = blockIdx.x * 256;

    hw2s[tid] = g_hw2[(size_t)b * UX + n0 + tid];
    Vs[tid] = V[n0 + tid];

    const __half* encB = g_ench + (size_t)b * Tx * ENCX;
    const __half* W1tB = g_W1th + (size_t)n0 * ENCX;

    int arw[4], ac16[4], brw[8], bc16[8];
#pragma unroll
    for (int i = 0; i < 4; i++) {
        int idx = i * 256 + tid;
        arw[i] = idx >> 3; ac16[i] = idx & 7;
    }
#pragma unroll
    for (int i = 0; i < 8; i++) {
        int idx = i * 256 + tid;
        brw[i] = idx >> 3; bc16[i] = idx & 7;
    }

#define SC_ISSUE(J) do { \
    int k0 = (J) * 64; int sb = (J) & 1; \
    uint32_t ab = smu + sb * SC_STAGE_A; \
    uint32_t bb = smu + SC_BS_OFF + sb * SC_STAGE_B; \
    _Pragma("unroll") \
    for (int i = 0; i < 4; i++) \
        cp_async16(ab + (uint32_t)(arw[i] * 144 + ac16[i] * 16), \
                   encB + (size_t)arw[i] * ENCX + k0 + ac16[i] * 8); \
    _Pragma("unroll") \
    for (int i = 0; i < 8; i++) \
        cp_async16(bb + (uint32_t)(brw[i] * 144 + bc16[i] * 16), \
                   W1tB + (size_t)brw[i] * ENCX + k0 + bc16[i] * 8); \
    CP_COMMIT(); } while (0)

    float acc[4][8][4] = {};

    SC_ISSUE(0);
    for (int j = 0; j < SC_NKT; j++) {
        CP_WAIT0();
        __syncthreads();
        if (j + 1 < SC_NKT) SC_ISSUE(j + 1);
        const uint32_t* Asb = (const uint32_t*)smraw + (j & 1) * (SC_STAGE_A / 4);
        const uint32_t* Bsb = (const uint32_t*)(smraw + SC_BS_OFF) + (j & 1) * (SC_STAGE_B / 4);
#pragma unroll
        for (int kk2 = 0; kk2 < 32; kk2 += 8) {
            unsigned afr[4][4], bfr[8][2];
#pragma unroll
            for (int i = 0; i < 4; i++) {
                int row = warp_m * 64 + i * 16 + g;
                afr[i][0] = Asb[row * HSTRW + kk2 + tig];
                afr[i][1] = Asb[(row + 8) * HSTRW + kk2 + tig];
                afr[i][2] = Asb[row * HSTRW + kk2 + tig + 4];
                afr[i][3] = Asb[(row + 8) * HSTRW + kk2 + tig + 4];
            }
#pragma unroll
            for (int jn = 0; jn < 8; jn++) {
                int col = warp_n * 64 + jn * 8 + g;
                bfr[jn][0] = Bsb[col * HSTRW + kk2 + tig];
                bfr[jn][1] = Bsb[col * HSTRW + kk2 + tig + 4];
            }
#pragma unroll
            for (int i = 0; i < 4; i++)
#pragma unroll
                for (int jn = 0; jn < 8; jn++) mma_f16(acc[i][jn], afr[i], bfr[jn]);
        }
    }

    __syncthreads();
#pragma unroll
    for (int i = 0; i < 4; i++) {
        float s0 = 0.f, s1 = 0.f;
#pragma unroll
        for (int jn = 0; jn < 8; jn++) {
            int nb = warp_n * 64 + jn * 8 + tig * 2;
#pragma unroll
            for (int c = 0; c < 2; c++) {
                int n = nb + c;
                s0 += tanhf(acc[i][jn][c] + hw2s[n]) * Vs[n];
                s1 += tanhf(acc[i][jn][2 + c] + hw2s[n]) * Vs[n];
            }
        }
        s0 += __shfl_xor_sync(0xffffffffu, s0, 1);
        s0 += __shfl_xor_sync(0xffffffffu, s0, 2);
        s1 += __shfl_xor_sync(0xffffffffu, s1, 1);
        s1 += __shfl_xor_sync(0xffffffffu, s1, 2);
        if (tig == 0) {
            int r0 = warp_m * 64 + i * 16 + g;
            red[r0 * 5 + warp_n] = s0;
            red[(r0 + 8) * 5 + warp_n] = s1;
        }
    }
    __syncthreads();
    if (tid < 128) {
        float s = red[tid * 5 + 0] + red[tid * 5 + 1] + red[tid * 5 + 2] + red[tid * 5 + 3];
        atomicAdd(&g_S[b * Tx + tid], s);
    }
}

// ---------------- softmax over T + emb gather ----------------
__global__ void k_softmax(const int* __restrict__ x, const float* __restrict__ E,
                          float* __restrict__ attn_out) {
    int b = blockIdx.x;
    int tid = threadIdx.x;
    __shared__ float sh[128];
    float s = g_S[b * Tx + tid];
    sh[tid] = s;
    __syncthreads();
    for (int off = 64; off; off >>= 1) {
        if (tid < off) sh[tid] = fmaxf(sh[tid], sh[tid + off]);
        __syncthreads();
    }
    float mx = sh[0];
    __syncthreads();
    float e = expf(s - mx);
    sh[tid] = e;
    __syncthreads();
    for (int off = 64; off; off >>= 1) {
        if (tid < off) sh[tid] = sh[tid] + sh[tid + off];
        __syncthreads();
    }
    float a = e / sh[0];
    g_attn[b * Tx + tid] = a;
    attn_out[b * Tx + tid] = a;
    int row = x[b];
    for (int e2 = tid; e2 < EMBX; e2 += 128)
        g_xt[(size_t)b * XDIM + ENCX + e2] = E[(size_t)row * EMBX + e2];
}

// ---------------- context (fp16 enc reads, 2 cols/thread) ----------------
__global__ void k_ctx() {
    int b = blockIdx.x;
    int ec2 = blockIdx.y * 256 + threadIdx.x;   // half2 column index
    __shared__ float attn_sh[128];
    if (threadIdx.x < 128) attn_sh[threadIdx.x] = g_attn[b * Tx + threadIdx.x];
    __syncthreads();
    const __half2* p = (const __half2*)(g_ench + (size_t)b * Tx * ENCX) + ec2;
    float cx = 0.f, cy = 0.f;
#pragma unroll 8
    for (int t = 0; t < Tx; t++) {
        float2 v = __half22float2(p[(size_t)t * (ENCX / 2)]);
        float a = attn_sh[t];
        cx += a * v.x;
        cy += a * v.y;
    }
    *(float2*)&g_xt[(size_t)b * XDIM + ec2 * 2] = make_float2(cx, cy);
}

// ---------------- gates ----------------
__global__ void k_gate(const float* __restrict__ Wx, const float* __restrict__ bg) {
    __shared__ float As[16][64];
    __shared__ float Bs[16][64];
    int tid = threadIdx.x;
    int m0 = blockIdx.y * 64;
    int nv0 = blockIdx.x * 64;
    int na0 = (nv0 < UX) ? nv0 : nv0 + UX;
    int ar = tid >> 2, ac = (tid & 3) << 2;
    int br = tid >> 4, bc = (tid & 15) << 2;
    int ty = tid >> 4, tx = tid & 15;
    float acc[4][4] = {};
    for (int k0 = 0; k0 < XDIM; k0 += 16) {
        float4 av = *(const float4*)&g_xt[(size_t)(m0 + ar) * XDIM + k0 + ac];
        float4 bv = *(const float4*)&Wx[(size_t)(k0 + br) * WXN + na0 + bc];
        __syncthreads();
        As[ac + 0][ar] = av.x; As[ac + 1][ar] = av.y;
        As[ac + 2][ar] = av.z; As[ac + 3][ar] = av.w;
        *(float4*)&Bs[br][bc] = bv;
        __syncthreads();
#pragma unroll
        for (int k = 0; k < 16; k++) {
            float ra[4], rb[4];
#pragma unroll
            for (int i = 0; i < 4; i++) ra[i] = As[k][ty * 4 + i];
#pragma unroll
            for (int j = 0; j < 4; j++) rb[j] = Bs[k][tx * 4 + j];
#pragma unroll
            for (int i = 0; i < 4; i++)
#pragma unroll
                for (int j = 0; j < 4; j++) acc[i][j] += ra[i] * rb[j];
        }
    }
#pragma unroll
    for (int i = 0; i < 4; i++) {
        int m = m0 + ty * 4 + i;
#pragma unroll
        for (int j = 0; j < 4; j++) {
            int nv = nv0 + tx * 4 + j;
            int na = na0 + tx * 4 + j;
            g_gx[(size_t)m * GXN + nv] = acc[i][j] + bg[na];
        }
    }
}

// ---------------- state = (1 - sigmoid(gz)) * tanh(ghh); + fp16 copy ---------
__global__ void k_state(float* __restrict__ out_state) {
    int i = blockIdx.x * blockDim.x + threadIdx.x;
    if (i >= Bx * UX) return;
    int bb = i >> 10, u = i & 1023;
    float gz = g_gx[(size_t)bb * GXN + u];
    float gh = g_gx[(size_t)bb * GXN + UX + u];
    float z = 1.f / (1.f + expf(-gz));
    float st = (1.f - z) * tanhf(gh);
    out_state[i] = st;
    g_stateh[i] = __float2half_rn(st);
}

// ============ logits GEMM (mma.sync fp16 + ldmatrix.trans B) =================
// M=256, N=32000, K=1024. BM=128, BN=128, BK=64. 128 threads, 4 warps 2x2,
// warptile 64x64. A [m][k] fp16 stride 144B; B [k][n] fp16 stride 272B.
// A tile = 128 rows x 8 chunks of 16B = 1024 chunks -> 8 chunks/thread.
#define LG_BS_OFF   36864
#define LG_ASTAGE   18432
#define LG_BSTAGE   17408
#define LG_SMEM_BYTES 71680
#define LG_NKT      16

__global__ void __launch_bounds__(128, 2)
k_logits_f16(const float* __restrict__ bfc, float* __restrict__ C) {
    extern __shared__ char smraw[];
    uint32_t smu = smem_to_u32(smraw);

    int tid = threadIdx.x;
    int lane = tid & 31, wid = tid >> 5;
    int warp_m = wid & 1, warp_n = wid >> 1;
    int g = lane >> 2, tig = lane & 3;
    int m0 = blockIdx.y * 128, n0 = blockIdx.x * 128;

    const __half* Ab = g_stateh + (size_t)m0 * UX;
    const __half* Bb = g_Wfch + n0;

    // A: 1024 16B chunks (8/thread, FIXED); B: 1024 chunks (8/thread)
    int am[8], ac16[8], bk[8], bn16[8];
#pragma unroll
    for (int i = 0; i < 8; i++) {
        int idx = i * 128 + tid;
        am[i] = idx >> 3; ac16[i] = idx & 7;
        bk[i] = idx >> 4; bn16[i] = idx & 15;
    }

    int lm_row = (lane & 7) + ((lane >> 3) & 1) * 8;
    int lm_col = (lane >> 4) * 8;

#define LG_ISSUE(J) do { \
    int k0 = (J) * 64; int sb = (J) & 1; \
    uint32_t ab = smu + sb * LG_ASTAGE; \
    uint32_t bb = smu + LG_BS_OFF + sb * LG_BSTAGE; \
    _Pragma("unroll") \
    for (int i = 0; i < 8; i++) { \
        cp_async16(ab + (uint32_t)(am[i] * 144 + ac16[i] * 16), \
                   Ab + (size_t)am[i] * UX + k0 + ac16[i] * 8); \
        cp_async16(bb + (uint32_t)(bk[i] * 272 + bn16[i] * 16), \
                   Bb + (size_t)(k0 + bk[i]) * VOCABX + bn16[i] * 8); \
    } \
    CP_COMMIT(); } while (0)

    float acc[4][8][4] = {};

    LG_ISSUE(0);
    for (int j = 0; j < LG_NKT; j++) {
        CP_WAIT0();
        __syncthreads();
        if (j + 1 < LG_NKT) LG_ISSUE(j + 1);
        const uint32_t* Asb = (const uint32_t*)smraw + (j & 1) * (LG_ASTAGE / 4);
        uint32_t bsBase = smu + LG_BS_OFF + (j & 1) * LG_BSTAGE;
#pragma unroll
        for (int s = 0; s < 4; s++) {           // k16 steps
            int kk2 = s * 8;
            unsigned afr[4][4], bfr[8][2];
#pragma unroll
            for (int i = 0; i < 4; i++) {
                int row = warp_m * 64 + i * 16 + g;
                afr[i][0] = Asb[row * HSTRW + kk2 + tig];
                afr[i][1] = Asb[(row + 8) * HSTRW + kk2 + tig];
                afr[i][2] = Asb[row * HSTRW + kk2 + tig + 4];
                afr[i][3] = Asb[(row + 8) * HSTRW + kk2 + tig + 4];
            }
#pragma unroll
            for (int jn2 = 0; jn2 < 4; jn2++) {
                uint32_t addr = bsBase +
                    (uint32_t)(s * 16 + lm_row) * 272 +
                    (uint32_t)(warp_n * 64 + jn2 * 16 + lm_col) * 2;
                ldmatrix_x4_trans(bfr[jn2 * 2][0], bfr[jn2 * 2][1],
                                  bfr[jn2 * 2 + 1][0], bfr[jn2 * 2 + 1][1], addr);
            }
#pragma unroll
            for (int i = 0; i < 4; i++)
#pragma unroll
                for (int jn = 0; jn < 8; jn++) mma_f16(acc[i][jn], afr[i], bfr[jn]);
        }
    }

#pragma unroll
    for (int i = 0; i < 4; i++) {
        int r = m0 + warp_m * 64 + i * 16 + g;
#pragma unroll
        for (int jn = 0; jn < 8; jn++) {
            int n = n0 + warp_n * 64 + jn * 8 + tig * 2;
            float bf0 = bfc[n], bf1 = bfc[n + 1];
            *(float2*)&C[(size_t)r * VOCABX + n] =
                make_float2(acc[i][jn][0] + bf0, acc[i][jn][1] + bf1);
            *(float2*)&C[(size_t)(r + 8) * VOCABX + n] =
                make_float2(acc[i][jn][2] + bf0, acc[i][jn][3] + bf1);
        }
    }
}

// ---------------- launcher (single stream, fused prologue) ----------------
extern "C" void kernel_launch(void* const* d_in, const int* in_sizes, int n_in,
                              void* d_out, int out_size) {
    const int*   x      = (const int*)d_in[0];
    const float* hidden = (const float*)d_in[1];
    const float* enc    = (const float*)d_in[2];
    const float* E      = (const float*)d_in[3];
    const float* W1     = (const float*)d_in[4];
    const float* b1     = (const float*)d_in[5];
    const float* W2     = (const float*)d_in[6];
    const float* b2     = (const float*)d_in[7];
    const float* V      = (const float*)d_in[8];
    const float* Wx     = (const float*)d_in[10];
    const float* b_gru  = (const float*)d_in[12];
    const float* Wfc    = (const float*)d_in[13];
    const float* bfc    = (const float*)d_in[14];

    float* out        = (float*)d_out;
    float* out_logits = out;
    float* out_state  = out + (size_t)Bx * VOCABX;
    float* out_attn   = out + (size_t)Bx * VOCABX + Bx * UX;

    cudaFuncSetAttribute(k_score_tc, cudaFuncAttributeMaxDynamicSharedMemorySize,
                         SC_SMEM_BYTES);
    cudaFuncSetAttribute(k_logits_f16, cudaFuncAttributeMaxDynamicSharedMemorySize,
                         LG_SMEM_BYTES);

    k_prologue<<<PB_TOTAL, 256>>>(enc, Wfc, b1, b2, W1, hidden, W2);
    k_score_tc<<<dim3(UX / 256, Bx), 256, SC_SMEM_BYTES>>>(V);
    k_softmax<<<Bx, 128>>>(x, E, out_attn);
    k_ctx<<<dim3(Bx, ENCX / 512), 256>>>();
    k_gate<<<dim3(GXN / 64, Bx / 64), 256>>>(Wx, b_gru);
    k_state<<<(Bx * UX + 255) / 256, 256>>>(out_state);
    k_logits_f16<<<dim3(VOCABX / 128, Bx / 128), 128, LG_SMEM_BYTES>>>(
        bfc, out_logits);
}